// round 13
// baseline (speedup 1.0000x reference)
#include <cuda_runtime.h>
#include <cuda_fp16.h>
#include <cstdint>

// Problem constants
#define BB   8
#define LL   4096
#define HH   512
#define PP   256
#define MM   (BB * LL)        // 32768
#define N1   (2 * PP)         // 512
#define CHUNK 128
#define NCH  (LL / CHUNK)     // 32
#define MH   (MM * HH)        // 16777216 (out float elements)
#define KTA  32               // A k_tiles (single fp16 plane, K'=512)
#define KTB  32               // B k_tiles
#define NKC  16               // k-chunks of 2 tiles
#define MT   (MM / 16)        // 2048 m_tiles
#define NT   (512 / 8)        // 64 n_tiles
#define APAD 24               // fp32 A smem row pitch (bank-conflict-free)

// ---------------------------------------------------------------------------
// Scratch (device globals)
//   g_XeF: fragment-major fp16 A for GEMM2 (from scan_conv)
//   g_W1F/g_W2F: fragment-major fp16 B
//   g_Buh: Bu in fp16 [m][512] (GEMM1 output, scan input)
// GEMM1 reads fp32 u directly (uconv fused away).
// ---------------------------------------------------------------------------
__device__ uint4  g_XeF[(size_t)MT * KTA * 32];   // 32 MB
__device__ uint2  g_W1F[KTB * NT * 32];           // 0.5 MB
__device__ uint2  g_W2F[KTB * NT * 32];           // 0.5 MB
__device__ float  g_invS1[N1];
__device__ __half g_Buh[(size_t)MM * N1];         // 32 MB
__device__ float g_LbR[PP], g_LbI[PP];
__device__ float g_ScR[PP], g_ScI[PP];
__device__ float g_PowR[(CHUNK + 1) * PP], g_PowI[(CHUNK + 1) * PP];
__device__ float g_CEndR[BB * NCH * PP], g_CEndI[BB * NCH * PP];
__device__ float g_CInR [BB * NCH * PP], g_CInI [BB * NCH * PP];

// ---------------------------------------------------------------------------
// Helpers
// ---------------------------------------------------------------------------
__device__ __forceinline__ uint32_t pk2h(__half a, __half b) {
    __half2 t; t.x = a; t.y = b;
    return *reinterpret_cast<uint32_t*>(&t);
}
__device__ __forceinline__ uint32_t h2u(__half2 h) {
    return *reinterpret_cast<uint32_t*>(&h);
}
__device__ __forceinline__ void mma16816h(float* d, const uint4& a, const uint2& b) {
    asm volatile(
        "mma.sync.aligned.m16n8k16.row.col.f32.f16.f16.f32 "
        "{%0,%1,%2,%3}, {%4,%5,%6,%7}, {%8,%9}, {%0,%1,%2,%3};"
        : "+f"(d[0]), "+f"(d[1]), "+f"(d[2]), "+f"(d[3])
        : "r"(a.x), "r"(a.y), "r"(a.z), "r"(a.w), "r"(b.x), "r"(b.y));
}
__device__ __forceinline__ void cpa16(void* smem, const void* g) {
    uint32_t s = (uint32_t)__cvta_generic_to_shared(smem);
    asm volatile("cp.async.cg.shared.global [%0], [%1], 16;" :: "r"(s), "l"(g));
}
#define CPC()  asm volatile("cp.async.commit_group;")
#define CPW2() asm volatile("cp.async.wait_group 2;")
#define CPW1() asm volatile("cp.async.wait_group 1;")
#define CPW0() asm volatile("cp.async.wait_group 0;")

// ---------------------------------------------------------------------------
// Kernel: Lambda_bar, scale, power table (double precision)
// ---------------------------------------------------------------------------
__global__ void setup_lambda_kernel(const float* __restrict__ Lre,
                                    const float* __restrict__ Lim,
                                    const float* __restrict__ log_step) {
    int p = threadIdx.x;
    double lr = (double)Lre[p];
    double li = (double)Lim[p];
    double dt = exp((double)log_step[p]);
    double xr = lr * dt, xi = li * dt;
    double e  = exp(xr);
    double Lbr = e * cos(xi);
    double Lbi = e * sin(xi);
    g_LbR[p] = (float)Lbr;
    g_LbI[p] = (float)Lbi;
    double d2 = lr * lr + li * li;
    double nr = Lbr - 1.0, ni = Lbi;
    g_ScR[p] = (float)((nr * lr + ni * li) / d2);
    g_ScI[p] = (float)((ni * lr - nr * li) / d2);
    double pr = 1.0, pi = 0.0;
    g_PowR[p] = 1.0f; g_PowI[p] = 0.0f;
    for (int l = 1; l <= CHUNK; l++) {
        double tr = pr * Lbr - pi * Lbi;
        double ti = pr * Lbi + pi * Lbr;
        pr = tr; pi = ti;
        g_PowR[l * PP + p] = (float)pr;
        g_PowI[l * PP + p] = (float)pi;
    }
}

// ---------------------------------------------------------------------------
// Kernel: build W1', W2' fragment-major fp16 (single plane, kt 0..31)
// W1 pow2-normalized per column n; g_invS1[n] un-normalizes in GEMM1 epilogue.
// ---------------------------------------------------------------------------
__global__ __launch_bounds__(256)
void setup_w_frag(const float* __restrict__ Bmat,   // (P,H,2)
                  const float* __restrict__ Cmat) { // (H,P,2)
    int t = blockIdx.x * 256 + threadIdx.x;         // < 32*64*32
    int lane = t & 31;
    int nt   = (t >> 5) & 63;
    int kst  = t >> 11;            // 0..31
    int n  = nt * 8 + (lane >> 2);
    int kb = kst * 16 + (lane & 3) * 2;

    int p = n & 255;
    float sr = g_ScR[p], si = g_ScI[p];
    float mag = sqrtf(sr * sr + si * si);
    int ke = (int)ceilf(log2f(mag));
    float s = exp2f((float)(-ke));          // exact power of two
    if (kst == 0) g_invS1[n] = exp2f((float)ke);

    __half o1[4], o2[4];
#pragma unroll
    for (int e = 0; e < 4; e++) {
        int k = kb + (e & 1) + 8 * (e >> 1);
        float w1, w2;
        {
            int h = k;
            float br = Bmat[(p * HH + h) * 2 + 0];
            float bi = Bmat[(p * HH + h) * 2 + 1];
            w1 = ((n < PP) ? (sr * br - si * bi) : (sr * bi + si * br)) * s;
        }
        {
            int pk = k & 255, h = n;
            float cr = Cmat[(h * PP + pk) * 2 + 0];
            float ci = Cmat[(h * PP + pk) * 2 + 1];
            w2 = (k < PP) ? (2.0f * cr) : (-2.0f * ci);
        }
        o1[e] = __float2half(w1);
        o2[e] = __float2half(w2);
    }
    int idx = (kst * NT + nt) * 32 + lane;
    g_W1F[idx] = make_uint2(pk2h(o1[0], o1[1]), pk2h(o1[2], o1[3]));
    g_W2F[idx] = make_uint2(pk2h(o2[0], o2[1]), pk2h(o2[2], o2[3]));
}

// ---------------------------------------------------------------------------
// GEMM1 (fused uconv): Bu_h[m][n] = fp16( invS1[n] * sum_k u[m][k] W1'[k][n] )
// A loaded as fp32 row-major into smem (pitch APAD=24 -> conflict-free
// fragment gather), converted to fp16 fragments on the fly.
// Block 128x128, 8 warps (2m x 4n), 3-stage cp.async. Dynamic smem 86KB.
// ---------------------------------------------------------------------------
__global__ __launch_bounds__(256, 2)
void gemm1_kernel(const float* __restrict__ u, const uint2* __restrict__ gB,
                  __half* __restrict__ Outh, const float* __restrict__ gS) {
    extern __shared__ __align__(16) float dyn[];
    float* sAf = dyn;                                   // [3][2][128][APAD]
    uint2* sB  = (uint2*)((char*)dyn + 3 * 2 * 128 * APAD * 4);  // [3][2][16][32]

    int tid = threadIdx.x, lane = tid & 31, wid = tid >> 5;
    int wm = wid >> 2, wn = wid & 3;
    int g = lane >> 2, t2 = lane & 3;
    int bm0 = blockIdx.y * 128;
    int bnt = blockIdx.x * 16;

    float acc[4][4][4];
#pragma unroll
    for (int i = 0; i < 4; i++)
#pragma unroll
        for (int j = 0; j < 4; j++)
#pragma unroll
            for (int q = 0; q < 4; q++) acc[i][j][q] = 0.0f;

    auto load = [&](int kc, int buf) {
        int k0 = kc * 32;
#pragma unroll
        for (int it = 0; it < 4; it++) {        // A: 1024 chunks of 4 floats
            int f = tid + it * 256;
            int ktl = f >> 9, rem = f & 511;
            int row = rem >> 2, c4 = (rem & 3) * 4;
            cpa16(&sAf[((buf * 2 + ktl) * 128 + row) * APAD + c4],
                  u + (size_t)(bm0 + row) * HH + k0 + ktl * 16 + c4);
        }
#pragma unroll
        for (int it = 0; it < 2; it++) {        // B fragments
            int f = tid + it * 256;
            int ktl = f >> 8, nt = (f >> 4) & 15, pr = f & 15;
            int kt = kc * 2 + ktl;
            cpa16(&sB[(((buf * 2 + ktl) * 16) + nt) * 32 + pr * 2],
                  (const uint4*)gB + (((size_t)kt * NT + bnt + nt) * 16 + pr));
        }
    };

    load(0, 0); CPC();
    load(1, 1); CPC();
    load(2, 2); CPC();

    for (int kc = 0; kc < NKC; kc++) {
        if (kc < NKC - 2) { CPW2(); } else if (kc == NKC - 2) { CPW1(); } else { CPW0(); }
        __syncthreads();
        int buf = kc % 3;
#pragma unroll
        for (int ktl = 0; ktl < 2; ktl++) {
            uint4 a[4]; uint2 b[4];
#pragma unroll
            for (int i = 0; i < 4; i++) {
                const float* r0p = &sAf[((buf * 2 + ktl) * 128 + wm * 64 + i * 16 + g) * APAD + t2 * 2];
                const float* r1p = r0p + 8 * APAD;
                float2 p00 = *(const float2*)(r0p);
                float2 p10 = *(const float2*)(r1p);
                float2 p01 = *(const float2*)(r0p + 8);
                float2 p11 = *(const float2*)(r1p + 8);
                a[i].x = h2u(__floats2half2_rn(p00.x, p00.y));
                a[i].y = h2u(__floats2half2_rn(p10.x, p10.y));
                a[i].z = h2u(__floats2half2_rn(p01.x, p01.y));
                a[i].w = h2u(__floats2half2_rn(p11.x, p11.y));
            }
#pragma unroll
            for (int j = 0; j < 4; j++)
                b[j] = sB[(((buf * 2 + ktl) * 16) + wn * 4 + j) * 32 + lane];
#pragma unroll
            for (int i = 0; i < 4; i++)
#pragma unroll
                for (int j = 0; j < 4; j++)
                    mma16816h(acc[i][j], a[i], b[j]);
        }
        __syncthreads();
        if (kc + 3 < NKC) { load(kc + 3, buf); CPC(); }
    }

    // Epilogue: scale by invS1[n], convert to fp16, store
#pragma unroll
    for (int i = 0; i < 4; i++) {
        int m0 = bm0 + wm * 64 + i * 16 + g;
#pragma unroll
        for (int j = 0; j < 4; j++) {
            int n0 = (bnt + wn * 4 + j) * 8 + t2 * 2;
            float2 s2 = *(const float2*)(gS + n0);
            __half2 v0 = __floats2half2_rn(acc[i][j][0] * s2.x, acc[i][j][1] * s2.y);
            __half2 v1 = __floats2half2_rn(acc[i][j][2] * s2.x, acc[i][j][3] * s2.y);
            *(__half2*)(Outh + (size_t)m0 * N1 + n0)       = v0;
            *(__half2*)(Outh + (size_t)(m0 + 8) * N1 + n0) = v1;
        }
    }
}

// ---------------------------------------------------------------------------
// GEMM2: out[m][n] = sum_k X'[m][k] W2'[k][n] + D[n]*U[m][n]
// A = fragment-major fp16 (g_XeF). Same proven R12 structure.
// ---------------------------------------------------------------------------
__global__ __launch_bounds__(256, 2)
void gemm2_kernel(const uint4* __restrict__ gA, const uint2* __restrict__ gB,
                  float* __restrict__ Out, const float* __restrict__ U,
                  const float* __restrict__ Dv) {
    __shared__ __align__(16) uint4 sA[3][2][8][32];    // 24 KB
    __shared__ __align__(16) uint2 sB[3][2][16][32];   // 12 KB

    int tid = threadIdx.x, lane = tid & 31, wid = tid >> 5;
    int wm = wid >> 2, wn = wid & 3;
    int bmt = blockIdx.y * 8;
    int bnt = blockIdx.x * 16;

    float acc[4][4][4];
#pragma unroll
    for (int i = 0; i < 4; i++)
#pragma unroll
        for (int j = 0; j < 4; j++)
#pragma unroll
            for (int q = 0; q < 4; q++) acc[i][j][q] = 0.0f;

    auto load = [&](int kc, int buf) {
        int kt0 = kc * 2;
#pragma unroll
        for (int it = 0; it < 2; it++) {
            int f = tid + it * 256;
            int ktl = f >> 8, mt = (f >> 5) & 7, ln = f & 31;
            cpa16(&sA[buf][ktl][mt][ln],
                  gA + (((size_t)(bmt + mt) * KTA + kt0 + ktl) * 32 + ln));
        }
#pragma unroll
        for (int it = 0; it < 2; it++) {
            int f = tid + it * 256;
            int ktl = f >> 8, nt = (f >> 4) & 15, pr = f & 15;
            cpa16(&sB[buf][ktl][nt][pr * 2],
                  (const uint4*)gB + (((size_t)(kt0 + ktl) * NT + bnt + nt) * 16 + pr));
        }
    };

    load(0, 0); CPC();
    load(1, 1); CPC();
    load(2, 2); CPC();

    for (int kc = 0; kc < NKC; kc++) {
        if (kc < NKC - 2) { CPW2(); } else if (kc == NKC - 2) { CPW1(); } else { CPW0(); }
        __syncthreads();
        int buf = kc % 3;
#pragma unroll
        for (int ktl = 0; ktl < 2; ktl++) {
            uint4 a[4]; uint2 b[4];
#pragma unroll
            for (int i = 0; i < 4; i++) a[i] = sA[buf][ktl][wm * 4 + i][lane];
#pragma unroll
            for (int j = 0; j < 4; j++) b[j] = sB[buf][ktl][wn * 4 + j][lane];
#pragma unroll
            for (int i = 0; i < 4; i++)
#pragma unroll
                for (int j = 0; j < 4; j++)
                    mma16816h(acc[i][j], a[i], b[j]);
        }
        __syncthreads();
        if (kc + 3 < NKC) { load(kc + 3, buf); CPC(); }
    }

    int g = lane >> 2, t2 = lane & 3;
#pragma unroll
    for (int i = 0; i < 4; i++) {
        int m0 = (bmt + wm * 4 + i) * 16 + g;
#pragma unroll
        for (int j = 0; j < 4; j++) {
            int n0 = (bnt + wn * 4 + j) * 8 + t2 * 2;
            float2 v0 = make_float2(acc[i][j][0], acc[i][j][1]);
            float2 v1 = make_float2(acc[i][j][2], acc[i][j][3]);
            float2 dv = *(const float2*)(Dv + n0);
            float2 u0 = *(const float2*)(U + (size_t)m0 * HH + n0);
            float2 u1 = *(const float2*)(U + (size_t)(m0 + 8) * HH + n0);
            v0.x += dv.x * u0.x; v0.y += dv.y * u0.y;
            v1.x += dv.x * u1.x; v1.y += dv.y * u1.y;
            *(float2*)(Out + (size_t)m0 * HH + n0)       = v0;
            *(float2*)(Out + (size_t)(m0 + 8) * HH + n0) = v1;
        }
    }
}

// ---------------------------------------------------------------------------
// Scan pass 1: chunk end-states only (reads fp16 Bu). grid = 256 blocks.
// ---------------------------------------------------------------------------
__global__ __launch_bounds__(PP)
void scan_ends_kernel() {
    int bc = blockIdx.x;
    int b = bc >> 5, c = bc & 31;
    int p = threadIdx.x;
    float ar = g_LbR[p], ai = g_LbI[p];
    float xr = 0.0f, xi = 0.0f;
    int m0 = b * LL + c * CHUNK;
#pragma unroll 1
    for (int l0 = 0; l0 < CHUNK; l0 += 8) {
        float br[8], bi8[8];
#pragma unroll
        for (int j = 0; j < 8; j++) {
            size_t idx = (size_t)(m0 + l0 + j) * N1 + p;
            br[j]  = __half2float(g_Buh[idx]);
            bi8[j] = __half2float(g_Buh[idx + PP]);
        }
#pragma unroll
        for (int j = 0; j < 8; j++) {
            float nr = fmaf(ar, xr, fmaf(-ai, xi, br[j]));
            float ni = fmaf(ar, xi, fmaf( ai, xr, bi8[j]));
            xr = nr; xi = ni;
        }
    }
    int base = (b * NCH + c) * PP + p;
    g_CEndR[base] = xr;
    g_CEndI[base] = xi;
}

// ---------------------------------------------------------------------------
// Scan pass 2: carry scan across chunks + state output.
// ---------------------------------------------------------------------------
__global__ __launch_bounds__(PP)
void scan_carry_kernel(float* __restrict__ out, int out_size) {
    int b = blockIdx.x;
    int p = threadIdx.x;
    float plr = g_PowR[CHUNK * PP + p];
    float pli = g_PowI[CHUNK * PP + p];
    float cr = 0.0f, ci = 0.0f;
#pragma unroll
    for (int c = 0; c < NCH; c++) {
        int base = (b * NCH + c) * PP + p;
        g_CInR[base] = cr;
        g_CInI[base] = ci;
        float er = g_CEndR[base], ei = g_CEndI[base];
        float nr = fmaf(plr, cr, fmaf(-pli, ci, er));
        float ni = fmaf(plr, ci, fmaf( pli, cr, ei));
        cr = nr; ci = ni;
    }
    if (out_size >= MH + 2 * BB * PP) {
        size_t tail = (size_t)MH + ((size_t)b * PP + p) * 2;
        out[tail]     = cr;
        out[tail + 1] = ci;
    } else {
        out[(size_t)MH + (size_t)b * PP + p] = cr;
    }
}

// ---------------------------------------------------------------------------
// Scan pass 3 (fused): re-scan chunk seeded with global carry-in, convert to
// single-plane fp16 fragments for GEMM2. grid = 256 blocks.
// ---------------------------------------------------------------------------
__global__ __launch_bounds__(256)
void scan_conv_kernel() {
    __shared__ float s[16][520];   // padded
    int bc = blockIdx.x;
    int b = bc >> 5, c = bc & 31;
    int p = threadIdx.x;
    int cb = (b * NCH + c) * PP + p;
    float xr = g_CInR[cb], xi = g_CInI[cb];
    float ar = g_LbR[p], ai = g_LbI[p];
    int m0 = b * LL + c * CHUNK;

#pragma unroll 1
    for (int g8 = 0; g8 < 8; g8++) {
        float br[16], bi16[16];
#pragma unroll
        for (int r = 0; r < 16; r++) {
            size_t idx = (size_t)(m0 + g8 * 16 + r) * N1 + p;
            br[r]   = __half2float(g_Buh[idx]);
            bi16[r] = __half2float(g_Buh[idx + PP]);
        }
#pragma unroll
        for (int r = 0; r < 16; r++) {
            float nr = fmaf(ar, xr, fmaf(-ai, xi, br[r]));
            float ni = fmaf(ar, xi, fmaf( ai, xr, bi16[r]));
            xr = nr; xi = ni;
            s[r][p]      = xr;
            s[r][p + PP] = xi;
        }
        __syncthreads();

        int mt = (m0 >> 4) + g8;
#pragma unroll
        for (int it = 0; it < 4; it++) {
            int task = threadIdx.x + it * 256;   // 0..1023
            int kst = task >> 5, lane = task & 31;
            int r0 = lane >> 2;
            int c0 = (kst << 4) + (lane & 3) * 2;
            float v[8] = { s[r0][c0],     s[r0][c0 + 1], s[r0 + 8][c0],     s[r0 + 8][c0 + 1],
                           s[r0][c0 + 8], s[r0][c0 + 9], s[r0 + 8][c0 + 8], s[r0 + 8][c0 + 9] };
            __half h[8];
#pragma unroll
            for (int e = 0; e < 8; e++) h[e] = __float2half(v[e]);
            uint4 hv = make_uint4(pk2h(h[0], h[1]), pk2h(h[2], h[3]), pk2h(h[4], h[5]), pk2h(h[6], h[7]));
            size_t i0 = ((size_t)mt * KTA + kst) * 32 + lane;
            g_XeF[i0] = hv;
        }
        __syncthreads();
    }
}

// ---------------------------------------------------------------------------
extern "C" void kernel_launch(void* const* d_in, const int* in_sizes, int n_in,
                              void* d_out, int out_size) {
    const float* u        = (const float*)d_in[0];  // (B,L,H)
    const float* Lre      = (const float*)d_in[1];  // (P,)
    const float* Lim      = (const float*)d_in[2];  // (P,)
    const float* Bmat     = (const float*)d_in[3];  // (P,H,2)
    const float* Cmat     = (const float*)d_in[4];  // (H,P,2)
    const float* Dv       = (const float*)d_in[5];  // (H,)
    const float* log_step = (const float*)d_in[6];  // (P,)
    float* out = (float*)d_out;

    void *pXeF, *pW1F, *pW2F, *pBuh, *pS1;
    cudaGetSymbolAddress(&pXeF, g_XeF);
    cudaGetSymbolAddress(&pW1F, g_W1F);
    cudaGetSymbolAddress(&pW2F, g_W2F);
    cudaGetSymbolAddress(&pBuh, g_Buh);
    cudaGetSymbolAddress(&pS1,  g_invS1);

    const int SMEM1 = 3 * 2 * 128 * APAD * 4 + 3 * 2 * 16 * 32 * 8;   // 86016
    static bool attr_done = false;
    if (!attr_done) {
        cudaFuncSetAttribute(gemm1_kernel,
                             cudaFuncAttributeMaxDynamicSharedMemorySize, SMEM1);
        attr_done = true;
    }

    setup_lambda_kernel<<<1, PP>>>(Lre, Lim, log_step);
    setup_w_frag<<<(KTB * NT * 32) / 256, 256>>>(Bmat, Cmat);

    // GEMM1 (uconv fused): Bu_h = fp16( (u @ W1') * invS1 )
    gemm1_kernel<<<dim3(4, 256), 256, SMEM1>>>(
        u, (const uint2*)pW1F, (__half*)pBuh, (const float*)pS1);

    scan_ends_kernel<<<BB * NCH, PP>>>();
    scan_carry_kernel<<<BB, PP>>>(out, out_size);
    scan_conv_kernel<<<BB * NCH, 256>>>();

    // GEMM2: out = X @ W2 + D*u
    gemm2_kernel<<<dim3(4, 256), 256>>>(
        (const uint4*)pXeF, (const uint2*)pW2F, out, u, Dv);
}

// round 14
// speedup vs baseline: 1.0737x; 1.0737x over previous
#include <cuda_runtime.h>
#include <cuda_fp16.h>
#include <cstdint>

// Problem constants
#define BB   8
#define LL   4096
#define HH   512
#define PP   256
#define MM   (BB * LL)        // 32768
#define N1   (2 * PP)         // 512
#define CHUNK 128
#define NCH  (LL / CHUNK)     // 32
#define MH   (MM * HH)        // 16777216 (out float elements)
#define KTA  32               // A k_tiles (single fp16 plane, K'=512)
#define KTB  32               // B k_tiles
#define NKC  16               // k-chunks of 2 tiles
#define MT   (MM / 16)        // 2048 m_tiles
#define NT   (512 / 8)        // 64 n_tiles

// ---------------------------------------------------------------------------
// Scratch (device globals)
//   g_UeF: fragment-major fp16 u (GEMM1 A; also GEMM2 epilogue u-source)
//   g_XeF: fragment-major fp16 X (GEMM2 A, from scan_conv)
//   g_W1F/g_W2F: fragment-major fp16 B
//   g_Buh: Bu fp16 [m][512] (GEMM1 out, scan in)
// ---------------------------------------------------------------------------
__device__ uint4  g_UeF[(size_t)MT * KTA * 32];   // 32 MB
__device__ uint4  g_XeF[(size_t)MT * KTA * 32];   // 32 MB
__device__ uint2  g_W1F[KTB * NT * 32];           // 0.5 MB
__device__ uint2  g_W2F[KTB * NT * 32];           // 0.5 MB
__device__ float  g_invS1[N1];
__device__ __half g_Buh[(size_t)MM * N1];         // 32 MB
__device__ float g_LbR[PP], g_LbI[PP];
__device__ float g_ScR[PP], g_ScI[PP];
__device__ float g_PowR[(CHUNK + 1) * PP], g_PowI[(CHUNK + 1) * PP];
__device__ float g_CEndR[BB * NCH * PP], g_CEndI[BB * NCH * PP];
__device__ float g_CInR [BB * NCH * PP], g_CInI [BB * NCH * PP];

// ---------------------------------------------------------------------------
// Helpers
// ---------------------------------------------------------------------------
__device__ __forceinline__ uint32_t pk2h(__half a, __half b) {
    __half2 t; t.x = a; t.y = b;
    return *reinterpret_cast<uint32_t*>(&t);
}
__device__ __forceinline__ void mma16816h(float* d, const uint4& a, const uint2& b) {
    asm volatile(
        "mma.sync.aligned.m16n8k16.row.col.f32.f16.f16.f32 "
        "{%0,%1,%2,%3}, {%4,%5,%6,%7}, {%8,%9}, {%0,%1,%2,%3};"
        : "+f"(d[0]), "+f"(d[1]), "+f"(d[2]), "+f"(d[3])
        : "r"(a.x), "r"(a.y), "r"(a.z), "r"(a.w), "r"(b.x), "r"(b.y));
}
__device__ __forceinline__ void cpa16(void* smem, const void* g) {
    uint32_t s = (uint32_t)__cvta_generic_to_shared(smem);
    asm volatile("cp.async.cg.shared.global [%0], [%1], 16;" :: "r"(s), "l"(g));
}
#define CPC()  asm volatile("cp.async.commit_group;")
#define CPW2() asm volatile("cp.async.wait_group 2;")
#define CPW1() asm volatile("cp.async.wait_group 1;")
#define CPW0() asm volatile("cp.async.wait_group 0;")

// ---------------------------------------------------------------------------
// Kernel: Lambda_bar, scale, power table (double precision)
// ---------------------------------------------------------------------------
__global__ void setup_lambda_kernel(const float* __restrict__ Lre,
                                    const float* __restrict__ Lim,
                                    const float* __restrict__ log_step) {
    int p = threadIdx.x;
    double lr = (double)Lre[p];
    double li = (double)Lim[p];
    double dt = exp((double)log_step[p]);
    double xr = lr * dt, xi = li * dt;
    double e  = exp(xr);
    double Lbr = e * cos(xi);
    double Lbi = e * sin(xi);
    g_LbR[p] = (float)Lbr;
    g_LbI[p] = (float)Lbi;
    double d2 = lr * lr + li * li;
    double nr = Lbr - 1.0, ni = Lbi;
    g_ScR[p] = (float)((nr * lr + ni * li) / d2);
    g_ScI[p] = (float)((ni * lr - nr * li) / d2);
    double pr = 1.0, pi = 0.0;
    g_PowR[p] = 1.0f; g_PowI[p] = 0.0f;
    for (int l = 1; l <= CHUNK; l++) {
        double tr = pr * Lbr - pi * Lbi;
        double ti = pr * Lbi + pi * Lbr;
        pr = tr; pi = ti;
        g_PowR[l * PP + p] = (float)pr;
        g_PowI[l * PP + p] = (float)pi;
    }
}

// ---------------------------------------------------------------------------
// Kernel: build W1', W2' fragment-major fp16 (single plane, kt 0..31)
// W1 pow2-normalized per column n; g_invS1[n] un-normalizes in GEMM1 epilogue.
// ---------------------------------------------------------------------------
__global__ __launch_bounds__(256)
void setup_w_frag(const float* __restrict__ Bmat,   // (P,H,2)
                  const float* __restrict__ Cmat) { // (H,P,2)
    int t = blockIdx.x * 256 + threadIdx.x;         // < 32*64*32
    int lane = t & 31;
    int nt   = (t >> 5) & 63;
    int kst  = t >> 11;            // 0..31
    int n  = nt * 8 + (lane >> 2);
    int kb = kst * 16 + (lane & 3) * 2;

    int p = n & 255;
    float sr = g_ScR[p], si = g_ScI[p];
    float mag = sqrtf(sr * sr + si * si);
    int ke = (int)ceilf(log2f(mag));
    float s = exp2f((float)(-ke));          // exact power of two
    if (kst == 0) g_invS1[n] = exp2f((float)ke);

    __half o1[4], o2[4];
#pragma unroll
    for (int e = 0; e < 4; e++) {
        int k = kb + (e & 1) + 8 * (e >> 1);
        float w1, w2;
        {
            int h = k;
            float br = Bmat[(p * HH + h) * 2 + 0];
            float bi = Bmat[(p * HH + h) * 2 + 1];
            w1 = ((n < PP) ? (sr * br - si * bi) : (sr * bi + si * br)) * s;
        }
        {
            int pk = k & 255, h = n;
            float cr = Cmat[(h * PP + pk) * 2 + 0];
            float ci = Cmat[(h * PP + pk) * 2 + 1];
            w2 = (k < PP) ? (2.0f * cr) : (-2.0f * ci);
        }
        o1[e] = __float2half(w1);
        o2[e] = __float2half(w2);
    }
    int idx = (kst * NT + nt) * 32 + lane;
    g_W1F[idx] = make_uint2(pk2h(o1[0], o1[1]), pk2h(o1[2], o1[3]));
    g_W2F[idx] = make_uint2(pk2h(o2[0], o2[1]), pk2h(o2[2], o2[3]));
}

// ---------------------------------------------------------------------------
// Kernel: u (fp32 [M][512]) -> g_UeF single fp16 plane (fragment-major)
// ---------------------------------------------------------------------------
__global__ __launch_bounds__(256)
void uconv_kernel(const float* __restrict__ u) {
    int t = blockIdx.x * 256 + threadIdx.x;   // < 2048*32*32
    int lane = t & 31;
    int kst  = (t >> 5) & 31;
    int mt   = t >> 10;
    int r0 = (mt << 4) + (lane >> 2);
    int c0 = (kst << 4) + (lane & 3) * 2;
    const float* row0 = u + (size_t)r0 * HH;
    const float* row1 = row0 + 8 * HH;
    float2 p00 = *(const float2*)(row0 + c0);
    float2 p10 = *(const float2*)(row1 + c0);
    float2 p01 = *(const float2*)(row0 + c0 + 8);
    float2 p11 = *(const float2*)(row1 + c0 + 8);
    float v[8] = {p00.x, p00.y, p10.x, p10.y, p01.x, p01.y, p11.x, p11.y};
    __half h[8];
#pragma unroll
    for (int e = 0; e < 8; e++) h[e] = __float2half(v[e]);
    uint4 hv = make_uint4(pk2h(h[0], h[1]), pk2h(h[2], h[3]), pk2h(h[4], h[5]), pk2h(h[6], h[7]));
    size_t i0 = ((size_t)mt * KTA + kst) * 32 + lane;
    g_UeF[i0] = hv;
}

// ---------------------------------------------------------------------------
// GEMM1: Bu_h[m][n] = fp16( invS1[n] * sum_k u'[m][k] W1'[k][n] )
// Fragment-major fp16 A (proven R12 path). Block 128x128, 8 warps, 3-stage.
// ---------------------------------------------------------------------------
__global__ __launch_bounds__(256, 2)
void gemm1_kernel(const uint4* __restrict__ gA, const uint2* __restrict__ gB,
                  __half* __restrict__ Outh, const float* __restrict__ gS) {
    __shared__ __align__(16) uint4 sA[3][2][8][32];    // 24 KB
    __shared__ __align__(16) uint2 sB[3][2][16][32];   // 12 KB

    int tid = threadIdx.x, lane = tid & 31, wid = tid >> 5;
    int wm = wid >> 2, wn = wid & 3;
    int bmt = blockIdx.y * 8;
    int bnt = blockIdx.x * 16;

    float acc[4][4][4];
#pragma unroll
    for (int i = 0; i < 4; i++)
#pragma unroll
        for (int j = 0; j < 4; j++)
#pragma unroll
            for (int q = 0; q < 4; q++) acc[i][j][q] = 0.0f;

    auto load = [&](int kc, int buf) {
        int kt0 = kc * 2;
#pragma unroll
        for (int it = 0; it < 2; it++) {
            int f = tid + it * 256;
            int ktl = f >> 8, mt = (f >> 5) & 7, ln = f & 31;
            cpa16(&sA[buf][ktl][mt][ln],
                  gA + (((size_t)(bmt + mt) * KTA + kt0 + ktl) * 32 + ln));
        }
#pragma unroll
        for (int it = 0; it < 2; it++) {
            int f = tid + it * 256;
            int ktl = f >> 8, nt = (f >> 4) & 15, pr = f & 15;
            cpa16(&sB[buf][ktl][nt][pr * 2],
                  (const uint4*)gB + (((size_t)(kt0 + ktl) * NT + bnt + nt) * 16 + pr));
        }
    };

    load(0, 0); CPC();
    load(1, 1); CPC();
    load(2, 2); CPC();

    for (int kc = 0; kc < NKC; kc++) {
        if (kc < NKC - 2) { CPW2(); } else if (kc == NKC - 2) { CPW1(); } else { CPW0(); }
        __syncthreads();
        int buf = kc % 3;
#pragma unroll
        for (int ktl = 0; ktl < 2; ktl++) {
            uint4 a[4]; uint2 b[4];
#pragma unroll
            for (int i = 0; i < 4; i++) a[i] = sA[buf][ktl][wm * 4 + i][lane];
#pragma unroll
            for (int j = 0; j < 4; j++) b[j] = sB[buf][ktl][wn * 4 + j][lane];
#pragma unroll
            for (int i = 0; i < 4; i++)
#pragma unroll
                for (int j = 0; j < 4; j++)
                    mma16816h(acc[i][j], a[i], b[j]);
        }
        __syncthreads();
        if (kc + 3 < NKC) { load(kc + 3, buf); CPC(); }
    }

    // Epilogue: scale by invS1[n], convert to fp16, store
    int g = lane >> 2, t2 = lane & 3;
#pragma unroll
    for (int i = 0; i < 4; i++) {
        int m0 = (bmt + wm * 4 + i) * 16 + g;
#pragma unroll
        for (int j = 0; j < 4; j++) {
            int n0 = (bnt + wn * 4 + j) * 8 + t2 * 2;
            float2 s2 = *(const float2*)(gS + n0);
            __half2 v0 = __floats2half2_rn(acc[i][j][0] * s2.x, acc[i][j][1] * s2.y);
            __half2 v1 = __floats2half2_rn(acc[i][j][2] * s2.x, acc[i][j][3] * s2.y);
            *(__half2*)(Outh + (size_t)m0 * N1 + n0)       = v0;
            *(__half2*)(Outh + (size_t)(m0 + 8) * N1 + n0) = v1;
        }
    }
}

// ---------------------------------------------------------------------------
// GEMM2: out[m][n] = sum_k X'[m][k] W2'[k][n] + D[n]*u[m][n]
// A = fragment-major fp16 (g_XeF); epilogue u read from g_UeF fragments
// (fp16, half the traffic of fp32 u).
// Fragment addressing: value pair (m,n..n+1) lives at
//   g_UeF[(m>>4)*KTA + (n>>4)][lane = (m&7)*4 + ((n>>1)&3)], component
//   comp = ((m>>3)&1) + 2*((n>>3)&1).
// ---------------------------------------------------------------------------
__global__ __launch_bounds__(256, 2)
void gemm2_kernel(const uint4* __restrict__ gA, const uint2* __restrict__ gB,
                  float* __restrict__ Out, const uint4* __restrict__ gU,
                  const float* __restrict__ Dv) {
    __shared__ __align__(16) uint4 sA[3][2][8][32];    // 24 KB
    __shared__ __align__(16) uint2 sB[3][2][16][32];   // 12 KB

    int tid = threadIdx.x, lane = tid & 31, wid = tid >> 5;
    int wm = wid >> 2, wn = wid & 3;
    int bmt = blockIdx.y * 8;
    int bnt = blockIdx.x * 16;

    float acc[4][4][4];
#pragma unroll
    for (int i = 0; i < 4; i++)
#pragma unroll
        for (int j = 0; j < 4; j++)
#pragma unroll
            for (int q = 0; q < 4; q++) acc[i][j][q] = 0.0f;

    auto load = [&](int kc, int buf) {
        int kt0 = kc * 2;
#pragma unroll
        for (int it = 0; it < 2; it++) {
            int f = tid + it * 256;
            int ktl = f >> 8, mt = (f >> 5) & 7, ln = f & 31;
            cpa16(&sA[buf][ktl][mt][ln],
                  gA + (((size_t)(bmt + mt) * KTA + kt0 + ktl) * 32 + ln));
        }
#pragma unroll
        for (int it = 0; it < 2; it++) {
            int f = tid + it * 256;
            int ktl = f >> 8, nt = (f >> 4) & 15, pr = f & 15;
            cpa16(&sB[buf][ktl][nt][pr * 2],
                  (const uint4*)gB + (((size_t)(kt0 + ktl) * NT + bnt + nt) * 16 + pr));
        }
    };

    load(0, 0); CPC();
    load(1, 1); CPC();
    load(2, 2); CPC();

    for (int kc = 0; kc < NKC; kc++) {
        if (kc < NKC - 2) { CPW2(); } else if (kc == NKC - 2) { CPW1(); } else { CPW0(); }
        __syncthreads();
        int buf = kc % 3;
#pragma unroll
        for (int ktl = 0; ktl < 2; ktl++) {
            uint4 a[4]; uint2 b[4];
#pragma unroll
            for (int i = 0; i < 4; i++) a[i] = sA[buf][ktl][wm * 4 + i][lane];
#pragma unroll
            for (int j = 0; j < 4; j++) b[j] = sB[buf][ktl][wn * 4 + j][lane];
#pragma unroll
            for (int i = 0; i < 4; i++)
#pragma unroll
                for (int j = 0; j < 4; j++)
                    mma16816h(acc[i][j], a[i], b[j]);
        }
        __syncthreads();
        if (kc + 3 < NKC) { load(kc + 3, buf); CPC(); }
    }

    int g = lane >> 2, t2 = lane & 3;
#pragma unroll
    for (int i = 0; i < 4; i++) {
        int mt_i = bmt + wm * 4 + i;          // m-tile index
        int m0 = mt_i * 16 + g;               // g < 8 -> row8(v0)=0, v1 row=+8
#pragma unroll
        for (int j = 0; j < 4; j++) {
            int ntile = bnt + wn * 4 + j;     // bnt, wn*4 even -> col8 = j&1
            int n0 = ntile * 8 + t2 * 2;
            int kt = ntile >> 1;
            int col8 = j & 1;
            const uint32_t* up =
                (const uint32_t*)(gU + (((size_t)mt_i * KTA + kt) * 32 + lane));
            uint32_t w0 = up[2 * col8];       // comp: row8=0
            uint32_t w1 = up[1 + 2 * col8];   // comp: row8=1
            __half2 uh0 = *reinterpret_cast<__half2*>(&w0);
            __half2 uh1 = *reinterpret_cast<__half2*>(&w1);
            float2 dv = *(const float2*)(Dv + n0);
            float2 v0 = make_float2(acc[i][j][0], acc[i][j][1]);
            float2 v1 = make_float2(acc[i][j][2], acc[i][j][3]);
            v0.x += dv.x * __low2float(uh0);  v0.y += dv.y * __high2float(uh0);
            v1.x += dv.x * __low2float(uh1);  v1.y += dv.y * __high2float(uh1);
            *(float2*)(Out + (size_t)m0 * HH + n0)       = v0;
            *(float2*)(Out + (size_t)(m0 + 8) * HH + n0) = v1;
        }
    }
}

// ---------------------------------------------------------------------------
// Scan pass 1: chunk end-states only (reads fp16 Bu). grid = 256 blocks.
// ---------------------------------------------------------------------------
__global__ __launch_bounds__(PP)
void scan_ends_kernel() {
    int bc = blockIdx.x;
    int b = bc >> 5, c = bc & 31;
    int p = threadIdx.x;
    float ar = g_LbR[p], ai = g_LbI[p];
    float xr = 0.0f, xi = 0.0f;
    int m0 = b * LL + c * CHUNK;
#pragma unroll 1
    for (int l0 = 0; l0 < CHUNK; l0 += 8) {
        float br[8], bi8[8];
#pragma unroll
        for (int j = 0; j < 8; j++) {
            size_t idx = (size_t)(m0 + l0 + j) * N1 + p;
            br[j]  = __half2float(g_Buh[idx]);
            bi8[j] = __half2float(g_Buh[idx + PP]);
        }
#pragma unroll
        for (int j = 0; j < 8; j++) {
            float nr = fmaf(ar, xr, fmaf(-ai, xi, br[j]));
            float ni = fmaf(ar, xi, fmaf( ai, xr, bi8[j]));
            xr = nr; xi = ni;
        }
    }
    int base = (b * NCH + c) * PP + p;
    g_CEndR[base] = xr;
    g_CEndI[base] = xi;
}

// ---------------------------------------------------------------------------
// Scan pass 2: carry scan across chunks + state output.
// ---------------------------------------------------------------------------
__global__ __launch_bounds__(PP)
void scan_carry_kernel(float* __restrict__ out, int out_size) {
    int b = blockIdx.x;
    int p = threadIdx.x;
    float plr = g_PowR[CHUNK * PP + p];
    float pli = g_PowI[CHUNK * PP + p];
    float cr = 0.0f, ci = 0.0f;
#pragma unroll
    for (int c = 0; c < NCH; c++) {
        int base = (b * NCH + c) * PP + p;
        g_CInR[base] = cr;
        g_CInI[base] = ci;
        float er = g_CEndR[base], ei = g_CEndI[base];
        float nr = fmaf(plr, cr, fmaf(-pli, ci, er));
        float ni = fmaf(plr, ci, fmaf( pli, cr, ei));
        cr = nr; ci = ni;
    }
    if (out_size >= MH + 2 * BB * PP) {
        size_t tail = (size_t)MH + ((size_t)b * PP + p) * 2;
        out[tail]     = cr;
        out[tail + 1] = ci;
    } else {
        out[(size_t)MH + (size_t)b * PP + p] = cr;
    }
}

// ---------------------------------------------------------------------------
// Scan pass 3 (fused): re-scan chunk seeded with global carry-in, convert to
// single-plane fp16 fragments for GEMM2. grid = 256 blocks.
// ---------------------------------------------------------------------------
__global__ __launch_bounds__(256)
void scan_conv_kernel() {
    __shared__ float s[16][520];   // padded
    int bc = blockIdx.x;
    int b = bc >> 5, c = bc & 31;
    int p = threadIdx.x;
    int cb = (b * NCH + c) * PP + p;
    float xr = g_CInR[cb], xi = g_CInI[cb];
    float ar = g_LbR[p], ai = g_LbI[p];
    int m0 = b * LL + c * CHUNK;

#pragma unroll 1
    for (int g8 = 0; g8 < 8; g8++) {
        float br[16], bi16[16];
#pragma unroll
        for (int r = 0; r < 16; r++) {
            size_t idx = (size_t)(m0 + g8 * 16 + r) * N1 + p;
            br[r]   = __half2float(g_Buh[idx]);
            bi16[r] = __half2float(g_Buh[idx + PP]);
        }
#pragma unroll
        for (int r = 0; r < 16; r++) {
            float nr = fmaf(ar, xr, fmaf(-ai, xi, br[r]));
            float ni = fmaf(ar, xi, fmaf( ai, xr, bi16[r]));
            xr = nr; xi = ni;
            s[r][p]      = xr;
            s[r][p + PP] = xi;
        }
        __syncthreads();

        int mt = (m0 >> 4) + g8;
#pragma unroll
        for (int it = 0; it < 4; it++) {
            int task = threadIdx.x + it * 256;   // 0..1023
            int kst = task >> 5, lane = task & 31;
            int r0 = lane >> 2;
            int c0 = (kst << 4) + (lane & 3) * 2;
            float v[8] = { s[r0][c0],     s[r0][c0 + 1], s[r0 + 8][c0],     s[r0 + 8][c0 + 1],
                           s[r0][c0 + 8], s[r0][c0 + 9], s[r0 + 8][c0 + 8], s[r0 + 8][c0 + 9] };
            __half h[8];
#pragma unroll
            for (int e = 0; e < 8; e++) h[e] = __float2half(v[e]);
            uint4 hv = make_uint4(pk2h(h[0], h[1]), pk2h(h[2], h[3]), pk2h(h[4], h[5]), pk2h(h[6], h[7]));
            size_t i0 = ((size_t)mt * KTA + kst) * 32 + lane;
            g_XeF[i0] = hv;
        }
        __syncthreads();
    }
}

// ---------------------------------------------------------------------------
extern "C" void kernel_launch(void* const* d_in, const int* in_sizes, int n_in,
                              void* d_out, int out_size) {
    const float* u        = (const float*)d_in[0];  // (B,L,H)
    const float* Lre      = (const float*)d_in[1];  // (P,)
    const float* Lim      = (const float*)d_in[2];  // (P,)
    const float* Bmat     = (const float*)d_in[3];  // (P,H,2)
    const float* Cmat     = (const float*)d_in[4];  // (H,P,2)
    const float* Dv       = (const float*)d_in[5];  // (H,)
    const float* log_step = (const float*)d_in[6];  // (P,)
    float* out = (float*)d_out;

    void *pUeF, *pXeF, *pW1F, *pW2F, *pBuh, *pS1;
    cudaGetSymbolAddress(&pUeF, g_UeF);
    cudaGetSymbolAddress(&pXeF, g_XeF);
    cudaGetSymbolAddress(&pW1F, g_W1F);
    cudaGetSymbolAddress(&pW2F, g_W2F);
    cudaGetSymbolAddress(&pBuh, g_Buh);
    cudaGetSymbolAddress(&pS1,  g_invS1);

    setup_lambda_kernel<<<1, PP>>>(Lre, Lim, log_step);
    setup_w_frag<<<(KTB * NT * 32) / 256, 256>>>(Bmat, Cmat);
    uconv_kernel<<<(MT * 32 * 32) / 256, 256>>>(u);

    // GEMM1: Bu_h = fp16( (u @ W1') * invS1 )
    gemm1_kernel<<<dim3(4, 256), 256>>>(
        (const uint4*)pUeF, (const uint2*)pW1F, (__half*)pBuh, (const float*)pS1);

    scan_ends_kernel<<<BB * NCH, PP>>>();
    scan_carry_kernel<<<BB, PP>>>(out, out_size);
    scan_conv_kernel<<<BB * NCH, 256>>>();

    // GEMM2: out = X @ W2 + D*u  (u from fp16 fragments)
    gemm2_kernel<<<dim3(4, 256), 256>>>(
        (const uint4*)pXeF, (const uint2*)pW2F, out, (const uint4*)pUeF, Dv);
}

// round 15
// speedup vs baseline: 1.2640x; 1.1772x over previous
#include <cuda_runtime.h>
#include <cuda_fp16.h>
#include <cstdint>

// Problem constants
#define BB   8
#define LL   4096
#define HH   512
#define PP   256
#define MM   (BB * LL)        // 32768
#define N1   (2 * PP)         // 512
#define CHUNK 64
#define NCH  (LL / CHUNK)     // 64
#define MH   (MM * HH)        // 16777216 (out float elements)
#define KTA  32               // A k_tiles (single fp16 plane, K'=512)
#define KTB  32               // B k_tiles
#define NKC  16               // k-chunks of 2 tiles
#define MT   (MM / 16)        // 2048 m_tiles
#define NT   (512 / 8)        // 64 n_tiles

// ---------------------------------------------------------------------------
// Scratch (device globals)
//   g_UeF: fragment-major fp16 u (GEMM1 A; also GEMM2 epilogue u-source)
//   g_XeF: fragment-major fp16 X (GEMM2 A, from scan_conv)
//   g_W1F/g_W2F: fragment-major fp16 B
//   g_Buh: Bu fp16 [m][512] (GEMM1 out, scan in)
// ---------------------------------------------------------------------------
__device__ uint4  g_UeF[(size_t)MT * KTA * 32];   // 32 MB
__device__ uint4  g_XeF[(size_t)MT * KTA * 32];   // 32 MB
__device__ uint2  g_W1F[KTB * NT * 32];           // 0.5 MB
__device__ uint2  g_W2F[KTB * NT * 32];           // 0.5 MB
__device__ float  g_invS1[N1];
__device__ __half g_Buh[(size_t)MM * N1];         // 32 MB
__device__ float g_LbR[PP], g_LbI[PP];
__device__ float g_ScR[PP], g_ScI[PP];
__device__ float g_PowR[(CHUNK + 1) * PP], g_PowI[(CHUNK + 1) * PP];
__device__ float g_CEndR[BB * NCH * PP], g_CEndI[BB * NCH * PP];
__device__ float g_CInR [BB * NCH * PP], g_CInI [BB * NCH * PP];

// ---------------------------------------------------------------------------
// Helpers
// ---------------------------------------------------------------------------
__device__ __forceinline__ uint32_t pk2h(__half a, __half b) {
    __half2 t; t.x = a; t.y = b;
    return *reinterpret_cast<uint32_t*>(&t);
}
__device__ __forceinline__ void mma16816h(float* d, const uint4& a, const uint2& b) {
    asm volatile(
        "mma.sync.aligned.m16n8k16.row.col.f32.f16.f16.f32 "
        "{%0,%1,%2,%3}, {%4,%5,%6,%7}, {%8,%9}, {%0,%1,%2,%3};"
        : "+f"(d[0]), "+f"(d[1]), "+f"(d[2]), "+f"(d[3])
        : "r"(a.x), "r"(a.y), "r"(a.z), "r"(a.w), "r"(b.x), "r"(b.y));
}
__device__ __forceinline__ void cpa16(void* smem, const void* g) {
    uint32_t s = (uint32_t)__cvta_generic_to_shared(smem);
    asm volatile("cp.async.cg.shared.global [%0], [%1], 16;" :: "r"(s), "l"(g));
}
#define CPC()  asm volatile("cp.async.commit_group;")
#define CPW1() asm volatile("cp.async.wait_group 1;")
#define CPW0() asm volatile("cp.async.wait_group 0;")

// ---------------------------------------------------------------------------
// Kernel: Lambda_bar, scale, power table (double precision)
// ---------------------------------------------------------------------------
__global__ void setup_lambda_kernel(const float* __restrict__ Lre,
                                    const float* __restrict__ Lim,
                                    const float* __restrict__ log_step) {
    int p = threadIdx.x;
    double lr = (double)Lre[p];
    double li = (double)Lim[p];
    double dt = exp((double)log_step[p]);
    double xr = lr * dt, xi = li * dt;
    double e  = exp(xr);
    double Lbr = e * cos(xi);
    double Lbi = e * sin(xi);
    g_LbR[p] = (float)Lbr;
    g_LbI[p] = (float)Lbi;
    double d2 = lr * lr + li * li;
    double nr = Lbr - 1.0, ni = Lbi;
    g_ScR[p] = (float)((nr * lr + ni * li) / d2);
    g_ScI[p] = (float)((ni * lr - nr * li) / d2);
    double pr = 1.0, pi = 0.0;
    g_PowR[p] = 1.0f; g_PowI[p] = 0.0f;
    for (int l = 1; l <= CHUNK; l++) {
        double tr = pr * Lbr - pi * Lbi;
        double ti = pr * Lbi + pi * Lbr;
        pr = tr; pi = ti;
        g_PowR[l * PP + p] = (float)pr;
        g_PowI[l * PP + p] = (float)pi;
    }
}

// ---------------------------------------------------------------------------
// Kernel: build W1', W2' fragment-major fp16 (single plane, kt 0..31)
// W1 pow2-normalized per column n; g_invS1[n] un-normalizes in GEMM1 epilogue.
// ---------------------------------------------------------------------------
__global__ __launch_bounds__(256)
void setup_w_frag(const float* __restrict__ Bmat,   // (P,H,2)
                  const float* __restrict__ Cmat) { // (H,P,2)
    int t = blockIdx.x * 256 + threadIdx.x;         // < 32*64*32
    int lane = t & 31;
    int nt   = (t >> 5) & 63;
    int kst  = t >> 11;            // 0..31
    int n  = nt * 8 + (lane >> 2);
    int kb = kst * 16 + (lane & 3) * 2;

    int p = n & 255;
    float sr = g_ScR[p], si = g_ScI[p];
    float mag = sqrtf(sr * sr + si * si);
    int ke = (int)ceilf(log2f(mag));
    float s = exp2f((float)(-ke));          // exact power of two
    if (kst == 0) g_invS1[n] = exp2f((float)ke);

    __half o1[4], o2[4];
#pragma unroll
    for (int e = 0; e < 4; e++) {
        int k = kb + (e & 1) + 8 * (e >> 1);
        float w1, w2;
        {
            int h = k;
            float br = Bmat[(p * HH + h) * 2 + 0];
            float bi = Bmat[(p * HH + h) * 2 + 1];
            w1 = ((n < PP) ? (sr * br - si * bi) : (sr * bi + si * br)) * s;
        }
        {
            int pk = k & 255, h = n;
            float cr = Cmat[(h * PP + pk) * 2 + 0];
            float ci = Cmat[(h * PP + pk) * 2 + 1];
            w2 = (k < PP) ? (2.0f * cr) : (-2.0f * ci);
        }
        o1[e] = __float2half(w1);
        o2[e] = __float2half(w2);
    }
    int idx = (kst * NT + nt) * 32 + lane;
    g_W1F[idx] = make_uint2(pk2h(o1[0], o1[1]), pk2h(o1[2], o1[3]));
    g_W2F[idx] = make_uint2(pk2h(o2[0], o2[1]), pk2h(o2[2], o2[3]));
}

// ---------------------------------------------------------------------------
// Kernel: u (fp32 [M][512]) -> g_UeF single fp16 plane (fragment-major)
// ---------------------------------------------------------------------------
__global__ __launch_bounds__(256)
void uconv_kernel(const float* __restrict__ u) {
    int t = blockIdx.x * 256 + threadIdx.x;   // < 2048*32*32
    int lane = t & 31;
    int kst  = (t >> 5) & 31;
    int mt   = t >> 10;
    int r0 = (mt << 4) + (lane >> 2);
    int c0 = (kst << 4) + (lane & 3) * 2;
    const float* row0 = u + (size_t)r0 * HH;
    const float* row1 = row0 + 8 * HH;
    float2 p00 = *(const float2*)(row0 + c0);
    float2 p10 = *(const float2*)(row1 + c0);
    float2 p01 = *(const float2*)(row0 + c0 + 8);
    float2 p11 = *(const float2*)(row1 + c0 + 8);
    float v[8] = {p00.x, p00.y, p10.x, p10.y, p01.x, p01.y, p11.x, p11.y};
    __half h[8];
#pragma unroll
    for (int e = 0; e < 8; e++) h[e] = __float2half(v[e]);
    uint4 hv = make_uint4(pk2h(h[0], h[1]), pk2h(h[2], h[3]), pk2h(h[4], h[5]), pk2h(h[6], h[7]));
    size_t i0 = ((size_t)mt * KTA + kst) * 32 + lane;
    g_UeF[i0] = hv;
}

// ---------------------------------------------------------------------------
// GEMM1: Bu_h[m][n] = fp16( invS1[n] * sum_k u'[m][k] W1'[k][n] )
// Fragment-major fp16 A. Block 128x128, 8 warps.
// 3-stage cp.async, SINGLE barrier per k-iteration (prefetch after barrier
// overwrites the stage consumed in the previous iteration).
// ---------------------------------------------------------------------------
__global__ __launch_bounds__(256, 2)
void gemm1_kernel(const uint4* __restrict__ gA, const uint2* __restrict__ gB,
                  __half* __restrict__ Outh, const float* __restrict__ gS) {
    __shared__ __align__(16) uint4 sA[3][2][8][32];    // 24 KB
    __shared__ __align__(16) uint2 sB[3][2][16][32];   // 12 KB

    int tid = threadIdx.x, lane = tid & 31, wid = tid >> 5;
    int wm = wid >> 2, wn = wid & 3;
    int bmt = blockIdx.y * 8;
    int bnt = blockIdx.x * 16;

    float acc[4][4][4];
#pragma unroll
    for (int i = 0; i < 4; i++)
#pragma unroll
        for (int j = 0; j < 4; j++)
#pragma unroll
            for (int q = 0; q < 4; q++) acc[i][j][q] = 0.0f;

    auto load = [&](int kc, int buf) {
        int kt0 = kc * 2;
#pragma unroll
        for (int it = 0; it < 2; it++) {
            int f = tid + it * 256;
            int ktl = f >> 8, mt = (f >> 5) & 7, ln = f & 31;
            cpa16(&sA[buf][ktl][mt][ln],
                  gA + (((size_t)(bmt + mt) * KTA + kt0 + ktl) * 32 + ln));
        }
#pragma unroll
        for (int it = 0; it < 2; it++) {
            int f = tid + it * 256;
            int ktl = f >> 8, nt = (f >> 4) & 15, pr = f & 15;
            cpa16(&sB[buf][ktl][nt][pr * 2],
                  (const uint4*)gB + (((size_t)(kt0 + ktl) * NT + bnt + nt) * 16 + pr));
        }
    };

    load(0, 0); CPC();
    load(1, 1); CPC();

    for (int kc = 0; kc < NKC; kc++) {
        if (kc < NKC - 1) { CPW1(); } else { CPW0(); }
        __syncthreads();
        if (kc + 2 < NKC) { load(kc + 2, (kc + 2) % 3); CPC(); }
        int buf = kc % 3;
#pragma unroll
        for (int ktl = 0; ktl < 2; ktl++) {
            uint4 a[4]; uint2 b[4];
#pragma unroll
            for (int i = 0; i < 4; i++) a[i] = sA[buf][ktl][wm * 4 + i][lane];
#pragma unroll
            for (int j = 0; j < 4; j++) b[j] = sB[buf][ktl][wn * 4 + j][lane];
#pragma unroll
            for (int i = 0; i < 4; i++)
#pragma unroll
                for (int j = 0; j < 4; j++)
                    mma16816h(acc[i][j], a[i], b[j]);
        }
    }

    // Epilogue: scale by invS1[n], convert to fp16, store
    int g = lane >> 2, t2 = lane & 3;
#pragma unroll
    for (int i = 0; i < 4; i++) {
        int m0 = (bmt + wm * 4 + i) * 16 + g;
#pragma unroll
        for (int j = 0; j < 4; j++) {
            int n0 = (bnt + wn * 4 + j) * 8 + t2 * 2;
            float2 s2 = *(const float2*)(gS + n0);
            __half2 v0 = __floats2half2_rn(acc[i][j][0] * s2.x, acc[i][j][1] * s2.y);
            __half2 v1 = __floats2half2_rn(acc[i][j][2] * s2.x, acc[i][j][3] * s2.y);
            *(__half2*)(Outh + (size_t)m0 * N1 + n0)       = v0;
            *(__half2*)(Outh + (size_t)(m0 + 8) * N1 + n0) = v1;
        }
    }
}

// ---------------------------------------------------------------------------
// GEMM2: out[m][n] = sum_k X'[m][k] W2'[k][n] + D[n]*u[m][n]
// A = fragment-major fp16 (g_XeF); epilogue u from g_UeF fp16 fragments.
// Single-barrier 3-stage pipeline (as GEMM1).
// ---------------------------------------------------------------------------
__global__ __launch_bounds__(256, 2)
void gemm2_kernel(const uint4* __restrict__ gA, const uint2* __restrict__ gB,
                  float* __restrict__ Out, const uint4* __restrict__ gU,
                  const float* __restrict__ Dv) {
    __shared__ __align__(16) uint4 sA[3][2][8][32];    // 24 KB
    __shared__ __align__(16) uint2 sB[3][2][16][32];   // 12 KB

    int tid = threadIdx.x, lane = tid & 31, wid = tid >> 5;
    int wm = wid >> 2, wn = wid & 3;
    int bmt = blockIdx.y * 8;
    int bnt = blockIdx.x * 16;

    float acc[4][4][4];
#pragma unroll
    for (int i = 0; i < 4; i++)
#pragma unroll
        for (int j = 0; j < 4; j++)
#pragma unroll
            for (int q = 0; q < 4; q++) acc[i][j][q] = 0.0f;

    auto load = [&](int kc, int buf) {
        int kt0 = kc * 2;
#pragma unroll
        for (int it = 0; it < 2; it++) {
            int f = tid + it * 256;
            int ktl = f >> 8, mt = (f >> 5) & 7, ln = f & 31;
            cpa16(&sA[buf][ktl][mt][ln],
                  gA + (((size_t)(bmt + mt) * KTA + kt0 + ktl) * 32 + ln));
        }
#pragma unroll
        for (int it = 0; it < 2; it++) {
            int f = tid + it * 256;
            int ktl = f >> 8, nt = (f >> 4) & 15, pr = f & 15;
            cpa16(&sB[buf][ktl][nt][pr * 2],
                  (const uint4*)gB + (((size_t)(kt0 + ktl) * NT + bnt + nt) * 16 + pr));
        }
    };

    load(0, 0); CPC();
    load(1, 1); CPC();

    for (int kc = 0; kc < NKC; kc++) {
        if (kc < NKC - 1) { CPW1(); } else { CPW0(); }
        __syncthreads();
        if (kc + 2 < NKC) { load(kc + 2, (kc + 2) % 3); CPC(); }
        int buf = kc % 3;
#pragma unroll
        for (int ktl = 0; ktl < 2; ktl++) {
            uint4 a[4]; uint2 b[4];
#pragma unroll
            for (int i = 0; i < 4; i++) a[i] = sA[buf][ktl][wm * 4 + i][lane];
#pragma unroll
            for (int j = 0; j < 4; j++) b[j] = sB[buf][ktl][wn * 4 + j][lane];
#pragma unroll
            for (int i = 0; i < 4; i++)
#pragma unroll
                for (int j = 0; j < 4; j++)
                    mma16816h(acc[i][j], a[i], b[j]);
        }
    }

    int g = lane >> 2, t2 = lane & 3;
#pragma unroll
    for (int i = 0; i < 4; i++) {
        int mt_i = bmt + wm * 4 + i;          // m-tile index
        int m0 = mt_i * 16 + g;
#pragma unroll
        for (int j = 0; j < 4; j++) {
            int ntile = bnt + wn * 4 + j;
            int n0 = ntile * 8 + t2 * 2;
            int kt = ntile >> 1;
            int col8 = j & 1;
            const uint32_t* up =
                (const uint32_t*)(gU + (((size_t)mt_i * KTA + kt) * 32 + lane));
            uint32_t w0 = up[2 * col8];
            uint32_t w1 = up[1 + 2 * col8];
            __half2 uh0 = *reinterpret_cast<__half2*>(&w0);
            __half2 uh1 = *reinterpret_cast<__half2*>(&w1);
            float2 dv = *(const float2*)(Dv + n0);
            float2 v0 = make_float2(acc[i][j][0], acc[i][j][1]);
            float2 v1 = make_float2(acc[i][j][2], acc[i][j][3]);
            v0.x += dv.x * __low2float(uh0);  v0.y += dv.y * __high2float(uh0);
            v1.x += dv.x * __low2float(uh1);  v1.y += dv.y * __high2float(uh1);
            *(float2*)(Out + (size_t)m0 * HH + n0)       = v0;
            *(float2*)(Out + (size_t)(m0 + 8) * HH + n0) = v1;
        }
    }
}

// ---------------------------------------------------------------------------
// Scan pass 1: chunk end-states only (reads fp16 Bu). grid = B*NCH = 512.
// ---------------------------------------------------------------------------
__global__ __launch_bounds__(PP)
void scan_ends_kernel() {
    int bc = blockIdx.x;
    int b = bc >> 6, c = bc & 63;
    int p = threadIdx.x;
    float ar = g_LbR[p], ai = g_LbI[p];
    float xr = 0.0f, xi = 0.0f;
    int m0 = b * LL + c * CHUNK;
#pragma unroll 1
    for (int l0 = 0; l0 < CHUNK; l0 += 8) {
        float br[8], bi8[8];
#pragma unroll
        for (int j = 0; j < 8; j++) {
            size_t idx = (size_t)(m0 + l0 + j) * N1 + p;
            br[j]  = __half2float(g_Buh[idx]);
            bi8[j] = __half2float(g_Buh[idx + PP]);
        }
#pragma unroll
        for (int j = 0; j < 8; j++) {
            float nr = fmaf(ar, xr, fmaf(-ai, xi, br[j]));
            float ni = fmaf(ar, xi, fmaf( ai, xr, bi8[j]));
            xr = nr; xi = ni;
        }
    }
    int base = (b * NCH + c) * PP + p;
    g_CEndR[base] = xr;
    g_CEndI[base] = xi;
}

// ---------------------------------------------------------------------------
// Scan pass 2: carry scan across chunks + state output.
// ---------------------------------------------------------------------------
__global__ __launch_bounds__(PP)
void scan_carry_kernel(float* __restrict__ out, int out_size) {
    int b = blockIdx.x;
    int p = threadIdx.x;
    float plr = g_PowR[CHUNK * PP + p];
    float pli = g_PowI[CHUNK * PP + p];
    float cr = 0.0f, ci = 0.0f;
#pragma unroll
    for (int c = 0; c < NCH; c++) {
        int base = (b * NCH + c) * PP + p;
        g_CInR[base] = cr;
        g_CInI[base] = ci;
        float er = g_CEndR[base], ei = g_CEndI[base];
        float nr = fmaf(plr, cr, fmaf(-pli, ci, er));
        float ni = fmaf(plr, ci, fmaf( pli, cr, ei));
        cr = nr; ci = ni;
    }
    if (out_size >= MH + 2 * BB * PP) {
        size_t tail = (size_t)MH + ((size_t)b * PP + p) * 2;
        out[tail]     = cr;
        out[tail + 1] = ci;
    } else {
        out[(size_t)MH + (size_t)b * PP + p] = cr;
    }
}

// ---------------------------------------------------------------------------
// Scan pass 3 (fused): re-scan chunk seeded with global carry-in, convert to
// single-plane fp16 fragments for GEMM2. grid = B*NCH = 512 blocks.
// ---------------------------------------------------------------------------
__global__ __launch_bounds__(256)
void scan_conv_kernel() {
    __shared__ float s[16][520];   // padded
    int bc = blockIdx.x;
    int b = bc >> 6, c = bc & 63;
    int p = threadIdx.x;
    int cb = (b * NCH + c) * PP + p;
    float xr = g_CInR[cb], xi = g_CInI[cb];
    float ar = g_LbR[p], ai = g_LbI[p];
    int m0 = b * LL + c * CHUNK;

#pragma unroll 1
    for (int g8 = 0; g8 < CHUNK / 16; g8++) {
        float br[16], bi16[16];
#pragma unroll
        for (int r = 0; r < 16; r++) {
            size_t idx = (size_t)(m0 + g8 * 16 + r) * N1 + p;
            br[r]   = __half2float(g_Buh[idx]);
            bi16[r] = __half2float(g_Buh[idx + PP]);
        }
#pragma unroll
        for (int r = 0; r < 16; r++) {
            float nr = fmaf(ar, xr, fmaf(-ai, xi, br[r]));
            float ni = fmaf(ar, xi, fmaf( ai, xr, bi16[r]));
            xr = nr; xi = ni;
            s[r][p]      = xr;
            s[r][p + PP] = xi;
        }
        __syncthreads();

        int mt = (m0 >> 4) + g8;
#pragma unroll
        for (int it = 0; it < 4; it++) {
            int task = threadIdx.x + it * 256;   // 0..1023
            int kst = task >> 5, lane = task & 31;
            int r0 = lane >> 2;
            int c0 = (kst << 4) + (lane & 3) * 2;
            float v[8] = { s[r0][c0],     s[r0][c0 + 1], s[r0 + 8][c0],     s[r0 + 8][c0 + 1],
                           s[r0][c0 + 8], s[r0][c0 + 9], s[r0 + 8][c0 + 8], s[r0 + 8][c0 + 9] };
            __half h[8];
#pragma unroll
            for (int e = 0; e < 8; e++) h[e] = __float2half(v[e]);
            uint4 hv = make_uint4(pk2h(h[0], h[1]), pk2h(h[2], h[3]), pk2h(h[4], h[5]), pk2h(h[6], h[7]));
            size_t i0 = ((size_t)mt * KTA + kst) * 32 + lane;
            g_XeF[i0] = hv;
        }
        __syncthreads();
    }
}

// ---------------------------------------------------------------------------
extern "C" void kernel_launch(void* const* d_in, const int* in_sizes, int n_in,
                              void* d_out, int out_size) {
    const float* u        = (const float*)d_in[0];  // (B,L,H)
    const float* Lre      = (const float*)d_in[1];  // (P,)
    const float* Lim      = (const float*)d_in[2];  // (P,)
    const float* Bmat     = (const float*)d_in[3];  // (P,H,2)
    const float* Cmat     = (const float*)d_in[4];  // (H,P,2)
    const float* Dv       = (const float*)d_in[5];  // (H,)
    const float* log_step = (const float*)d_in[6];  // (P,)
    float* out = (float*)d_out;

    void *pUeF, *pXeF, *pW1F, *pW2F, *pBuh, *pS1;
    cudaGetSymbolAddress(&pUeF, g_UeF);
    cudaGetSymbolAddress(&pXeF, g_XeF);
    cudaGetSymbolAddress(&pW1F, g_W1F);
    cudaGetSymbolAddress(&pW2F, g_W2F);
    cudaGetSymbolAddress(&pBuh, g_Buh);
    cudaGetSymbolAddress(&pS1,  g_invS1);

    setup_lambda_kernel<<<1, PP>>>(Lre, Lim, log_step);
    setup_w_frag<<<(KTB * NT * 32) / 256, 256>>>(Bmat, Cmat);
    uconv_kernel<<<(MT * 32 * 32) / 256, 256>>>(u);

    // GEMM1: Bu_h = fp16( (u @ W1') * invS1 )
    gemm1_kernel<<<dim3(4, 256), 256>>>(
        (const uint4*)pUeF, (const uint2*)pW1F, (__half*)pBuh, (const float*)pS1);

    scan_ends_kernel<<<BB * NCH, PP>>>();
    scan_carry_kernel<<<BB, PP>>>(out, out_size);
    scan_conv_kernel<<<BB * NCH, 256>>>();

    // GEMM2: out = X @ W2 + D*u  (u from fp16 fragments)
    gemm2_kernel<<<dim3(4, 256), 256>>>(
        (const uint4*)pXeF, (const uint2*)pW2F, out, (const uint4*)pUeF, Dv);
}

// round 16
// speedup vs baseline: 1.4844x; 1.1744x over previous
#include <cuda_runtime.h>
#include <cuda_fp16.h>
#include <cstdint>

// Problem constants
#define BB   8
#define LL   4096
#define HH   512
#define PP   256
#define MM   (BB * LL)        // 32768
#define N1   (2 * PP)         // 512
#define CHUNK 64
#define NCH  (LL / CHUNK)     // 64
#define MH   (MM * HH)        // 16777216 (out float elements)
#define KTA  32               // A k_tiles (single fp16 plane, K'=512)
#define KTB  32               // B k_tiles
#define NKC  16               // k-chunks of 2 tiles
#define MT   (MM / 16)        // 2048 m_tiles
#define NT   (512 / 8)        // 64 n_tiles

// prep kernel grid partition
#define PREP_POW_BLOCKS 65                  // (CHUNK+1)*PP / 256
#define PREP_W_BLOCKS   256                 // 32*64*32 / 256
#define PREP_U_BLOCKS   (MT * 4)            // MT*1024/256 = 8192
#define PREP_BLOCKS     (PREP_POW_BLOCKS + PREP_W_BLOCKS + PREP_U_BLOCKS)

// ---------------------------------------------------------------------------
// Scratch (device globals)
// ---------------------------------------------------------------------------
__device__ uint4  g_UeF[(size_t)MT * KTA * 32];   // 32 MB
__device__ uint4  g_XeF[(size_t)MT * KTA * 32];   // 32 MB
__device__ uint2  g_W1F[KTB * NT * 32];           // 0.5 MB
__device__ uint2  g_W2F[KTB * NT * 32];           // 0.5 MB
__device__ float  g_invS1[N1];
__device__ __half g_Buh[(size_t)MM * N1];         // 32 MB
__device__ float g_LbR[PP], g_LbI[PP];
__device__ float g_PowR[(CHUNK + 1) * PP], g_PowI[(CHUNK + 1) * PP];
__device__ float g_CEndR[BB * NCH * PP], g_CEndI[BB * NCH * PP];
__device__ float g_CInR [BB * NCH * PP], g_CInI [BB * NCH * PP];

// ---------------------------------------------------------------------------
// Helpers
// ---------------------------------------------------------------------------
__device__ __forceinline__ uint32_t pk2h(__half a, __half b) {
    __half2 t; t.x = a; t.y = b;
    return *reinterpret_cast<uint32_t*>(&t);
}
__device__ __forceinline__ void mma16816h(float* d, const uint4& a, const uint2& b) {
    asm volatile(
        "mma.sync.aligned.m16n8k16.row.col.f32.f16.f16.f32 "
        "{%0,%1,%2,%3}, {%4,%5,%6,%7}, {%8,%9}, {%0,%1,%2,%3};"
        : "+f"(d[0]), "+f"(d[1]), "+f"(d[2]), "+f"(d[3])
        : "r"(a.x), "r"(a.y), "r"(a.z), "r"(a.w), "r"(b.x), "r"(b.y));
}
__device__ __forceinline__ void cpa16(void* smem, const void* g) {
    uint32_t s = (uint32_t)__cvta_generic_to_shared(smem);
    asm volatile("cp.async.cg.shared.global [%0], [%1], 16;" :: "r"(s), "l"(g));
}
#define CPC()  asm volatile("cp.async.commit_group;")
#define CPW1() asm volatile("cp.async.wait_group 1;")
#define CPW0() asm volatile("cp.async.wait_group 0;")

// ---------------------------------------------------------------------------
// Fused prep kernel: [0,65) power table + Lambda_bar; [65,321) W fragments;
// [321, ...) u -> fragment-major fp16. All three partitions independent.
// ---------------------------------------------------------------------------
__global__ __launch_bounds__(256)
void prep_kernel(const float* __restrict__ Lre, const float* __restrict__ Lim,
                 const float* __restrict__ log_step,
                 const float* __restrict__ Bmat,   // (P,H,2)
                 const float* __restrict__ Cmat,   // (H,P,2)
                 const float* __restrict__ u) {
    int bid = blockIdx.x;
    if (bid < PREP_POW_BLOCKS) {
        // --- power table: Pow[l][p] = Lb^l computed directly (no serial chain)
        int idx = bid * 256 + threadIdx.x;
        if (idx >= (CHUNK + 1) * PP) return;
        int l = idx >> 8;          // 0..64
        int p = idx & 255;
        double lr = (double)Lre[p];
        double li = (double)Lim[p];
        double dt = exp((double)log_step[p]);
        double xr = lr * dt, xi = li * dt;
        double el = exp(xr * (double)l);
        double ang = xi * (double)l;
        g_PowR[l * PP + p] = (float)(el * cos(ang));
        g_PowI[l * PP + p] = (float)(el * sin(ang));
        if (l == 1) {
            double e = exp(xr);
            g_LbR[p] = (float)(e * cos(xi));
            g_LbI[p] = (float)(e * sin(xi));
        }
    } else if (bid < PREP_POW_BLOCKS + PREP_W_BLOCKS) {
        // --- W1'/W2' fragment-major fp16 (single plane); Sc recomputed locally
        int t = (bid - PREP_POW_BLOCKS) * 256 + threadIdx.x;   // < 32*64*32
        int lane = t & 31;
        int nt   = (t >> 5) & 63;
        int kst  = t >> 11;            // 0..31
        int n  = nt * 8 + (lane >> 2);
        int kb = kst * 16 + (lane & 3) * 2;

        int p = n & 255;
        // Sc = (Lb - 1) / Lambda in double (same math as before)
        double lr = (double)Lre[p];
        double li = (double)Lim[p];
        double dt = exp((double)log_step[p]);
        double xr = lr * dt, xi = li * dt;
        double e  = exp(xr);
        double Lbr = e * cos(xi), Lbi = e * sin(xi);
        double d2 = lr * lr + li * li;
        double nr = Lbr - 1.0, ni = Lbi;
        float sr = (float)((nr * lr + ni * li) / d2);
        float si = (float)((ni * lr - nr * li) / d2);

        float mag = sqrtf(sr * sr + si * si);
        int ke = (int)ceilf(log2f(mag));
        float s = exp2f((float)(-ke));          // exact power of two
        if (kst == 0) g_invS1[n] = exp2f((float)ke);

        __half o1[4], o2[4];
#pragma unroll
        for (int e2 = 0; e2 < 4; e2++) {
            int k = kb + (e2 & 1) + 8 * (e2 >> 1);
            float w1, w2;
            {
                int h = k;
                float br = Bmat[(p * HH + h) * 2 + 0];
                float bi = Bmat[(p * HH + h) * 2 + 1];
                w1 = ((n < PP) ? (sr * br - si * bi) : (sr * bi + si * br)) * s;
            }
            {
                int pk = k & 255, h = n;
                float cr = Cmat[(h * PP + pk) * 2 + 0];
                float ci = Cmat[(h * PP + pk) * 2 + 1];
                w2 = (k < PP) ? (2.0f * cr) : (-2.0f * ci);
            }
            o1[e2] = __float2half(w1);
            o2[e2] = __float2half(w2);
        }
        int idx = (kst * NT + nt) * 32 + lane;
        g_W1F[idx] = make_uint2(pk2h(o1[0], o1[1]), pk2h(o1[2], o1[3]));
        g_W2F[idx] = make_uint2(pk2h(o2[0], o2[1]), pk2h(o2[2], o2[3]));
    } else {
        // --- u (fp32 [M][512]) -> g_UeF fragment-major fp16
        int t = (bid - PREP_POW_BLOCKS - PREP_W_BLOCKS) * 256 + threadIdx.x;
        int lane = t & 31;
        int kst  = (t >> 5) & 31;
        int mt   = t >> 10;
        int r0 = (mt << 4) + (lane >> 2);
        int c0 = (kst << 4) + (lane & 3) * 2;
        const float* row0 = u + (size_t)r0 * HH;
        const float* row1 = row0 + 8 * HH;
        float2 p00 = *(const float2*)(row0 + c0);
        float2 p10 = *(const float2*)(row1 + c0);
        float2 p01 = *(const float2*)(row0 + c0 + 8);
        float2 p11 = *(const float2*)(row1 + c0 + 8);
        float v[8] = {p00.x, p00.y, p10.x, p10.y, p01.x, p01.y, p11.x, p11.y};
        __half h[8];
#pragma unroll
        for (int e = 0; e < 8; e++) h[e] = __float2half(v[e]);
        uint4 hv = make_uint4(pk2h(h[0], h[1]), pk2h(h[2], h[3]),
                              pk2h(h[4], h[5]), pk2h(h[6], h[7]));
        size_t i0 = ((size_t)mt * KTA + kst) * 32 + lane;
        g_UeF[i0] = hv;
    }
}

// ---------------------------------------------------------------------------
// GEMM1: Bu_h[m][n] = fp16( invS1[n] * sum_k u'[m][k] W1'[k][n] )
// Fragment-major fp16 A. Block 128x128, 8 warps, single-barrier 3-stage.
// ---------------------------------------------------------------------------
__global__ __launch_bounds__(256, 2)
void gemm1_kernel(const uint4* __restrict__ gA, const uint2* __restrict__ gB,
                  __half* __restrict__ Outh, const float* __restrict__ gS) {
    __shared__ __align__(16) uint4 sA[3][2][8][32];
    __shared__ __align__(16) uint2 sB[3][2][16][32];

    int tid = threadIdx.x, lane = tid & 31, wid = tid >> 5;
    int wm = wid >> 2, wn = wid & 3;
    int bmt = blockIdx.y * 8;
    int bnt = blockIdx.x * 16;

    float acc[4][4][4];
#pragma unroll
    for (int i = 0; i < 4; i++)
#pragma unroll
        for (int j = 0; j < 4; j++)
#pragma unroll
            for (int q = 0; q < 4; q++) acc[i][j][q] = 0.0f;

    auto load = [&](int kc, int buf) {
        int kt0 = kc * 2;
#pragma unroll
        for (int it = 0; it < 2; it++) {
            int f = tid + it * 256;
            int ktl = f >> 8, mt = (f >> 5) & 7, ln = f & 31;
            cpa16(&sA[buf][ktl][mt][ln],
                  gA + (((size_t)(bmt + mt) * KTA + kt0 + ktl) * 32 + ln));
        }
#pragma unroll
        for (int it = 0; it < 2; it++) {
            int f = tid + it * 256;
            int ktl = f >> 8, nt = (f >> 4) & 15, pr = f & 15;
            cpa16(&sB[buf][ktl][nt][pr * 2],
                  (const uint4*)gB + (((size_t)(kt0 + ktl) * NT + bnt + nt) * 16 + pr));
        }
    };

    load(0, 0); CPC();
    load(1, 1); CPC();

    for (int kc = 0; kc < NKC; kc++) {
        if (kc < NKC - 1) { CPW1(); } else { CPW0(); }
        __syncthreads();
        if (kc + 2 < NKC) { load(kc + 2, (kc + 2) % 3); CPC(); }
        int buf = kc % 3;
#pragma unroll
        for (int ktl = 0; ktl < 2; ktl++) {
            uint4 a[4]; uint2 b[4];
#pragma unroll
            for (int i = 0; i < 4; i++) a[i] = sA[buf][ktl][wm * 4 + i][lane];
#pragma unroll
            for (int j = 0; j < 4; j++) b[j] = sB[buf][ktl][wn * 4 + j][lane];
#pragma unroll
            for (int i = 0; i < 4; i++)
#pragma unroll
                for (int j = 0; j < 4; j++)
                    mma16816h(acc[i][j], a[i], b[j]);
        }
    }

    int g = lane >> 2, t2 = lane & 3;
#pragma unroll
    for (int i = 0; i < 4; i++) {
        int m0 = (bmt + wm * 4 + i) * 16 + g;
#pragma unroll
        for (int j = 0; j < 4; j++) {
            int n0 = (bnt + wn * 4 + j) * 8 + t2 * 2;
            float2 s2 = *(const float2*)(gS + n0);
            __half2 v0 = __floats2half2_rn(acc[i][j][0] * s2.x, acc[i][j][1] * s2.y);
            __half2 v1 = __floats2half2_rn(acc[i][j][2] * s2.x, acc[i][j][3] * s2.y);
            *(__half2*)(Outh + (size_t)m0 * N1 + n0)       = v0;
            *(__half2*)(Outh + (size_t)(m0 + 8) * N1 + n0) = v1;
        }
    }
}

// ---------------------------------------------------------------------------
// GEMM2: out[m][n] = sum_k X'[m][k] W2'[k][n] + D[n]*u[m][n]
// A = fragment-major fp16 (g_XeF); epilogue u from g_UeF fp16 fragments.
// ---------------------------------------------------------------------------
__global__ __launch_bounds__(256, 2)
void gemm2_kernel(const uint4* __restrict__ gA, const uint2* __restrict__ gB,
                  float* __restrict__ Out, const uint4* __restrict__ gU,
                  const float* __restrict__ Dv) {
    __shared__ __align__(16) uint4 sA[3][2][8][32];
    __shared__ __align__(16) uint2 sB[3][2][16][32];

    int tid = threadIdx.x, lane = tid & 31, wid = tid >> 5;
    int wm = wid >> 2, wn = wid & 3;
    int bmt = blockIdx.y * 8;
    int bnt = blockIdx.x * 16;

    float acc[4][4][4];
#pragma unroll
    for (int i = 0; i < 4; i++)
#pragma unroll
        for (int j = 0; j < 4; j++)
#pragma unroll
            for (int q = 0; q < 4; q++) acc[i][j][q] = 0.0f;

    auto load = [&](int kc, int buf) {
        int kt0 = kc * 2;
#pragma unroll
        for (int it = 0; it < 2; it++) {
            int f = tid + it * 256;
            int ktl = f >> 8, mt = (f >> 5) & 7, ln = f & 31;
            cpa16(&sA[buf][ktl][mt][ln],
                  gA + (((size_t)(bmt + mt) * KTA + kt0 + ktl) * 32 + ln));
        }
#pragma unroll
        for (int it = 0; it < 2; it++) {
            int f = tid + it * 256;
            int ktl = f >> 8, nt = (f >> 4) & 15, pr = f & 15;
            cpa16(&sB[buf][ktl][nt][pr * 2],
                  (const uint4*)gB + (((size_t)(kt0 + ktl) * NT + bnt + nt) * 16 + pr));
        }
    };

    load(0, 0); CPC();
    load(1, 1); CPC();

    for (int kc = 0; kc < NKC; kc++) {
        if (kc < NKC - 1) { CPW1(); } else { CPW0(); }
        __syncthreads();
        if (kc + 2 < NKC) { load(kc + 2, (kc + 2) % 3); CPC(); }
        int buf = kc % 3;
#pragma unroll
        for (int ktl = 0; ktl < 2; ktl++) {
            uint4 a[4]; uint2 b[4];
#pragma unroll
            for (int i = 0; i < 4; i++) a[i] = sA[buf][ktl][wm * 4 + i][lane];
#pragma unroll
            for (int j = 0; j < 4; j++) b[j] = sB[buf][ktl][wn * 4 + j][lane];
#pragma unroll
            for (int i = 0; i < 4; i++)
#pragma unroll
                for (int j = 0; j < 4; j++)
                    mma16816h(acc[i][j], a[i], b[j]);
        }
    }

    int g = lane >> 2, t2 = lane & 3;
#pragma unroll
    for (int i = 0; i < 4; i++) {
        int mt_i = bmt + wm * 4 + i;
        int m0 = mt_i * 16 + g;
#pragma unroll
        for (int j = 0; j < 4; j++) {
            int ntile = bnt + wn * 4 + j;
            int n0 = ntile * 8 + t2 * 2;
            int kt = ntile >> 1;
            int col8 = j & 1;
            const uint32_t* up =
                (const uint32_t*)(gU + (((size_t)mt_i * KTA + kt) * 32 + lane));
            uint32_t w0 = up[2 * col8];
            uint32_t w1 = up[1 + 2 * col8];
            __half2 uh0 = *reinterpret_cast<__half2*>(&w0);
            __half2 uh1 = *reinterpret_cast<__half2*>(&w1);
            float2 dv = *(const float2*)(Dv + n0);
            float2 v0 = make_float2(acc[i][j][0], acc[i][j][1]);
            float2 v1 = make_float2(acc[i][j][2], acc[i][j][3]);
            v0.x += dv.x * __low2float(uh0);  v0.y += dv.y * __high2float(uh0);
            v1.x += dv.x * __low2float(uh1);  v1.y += dv.y * __high2float(uh1);
            *(float2*)(Out + (size_t)m0 * HH + n0)       = v0;
            *(float2*)(Out + (size_t)(m0 + 8) * HH + n0) = v1;
        }
    }
}

// ---------------------------------------------------------------------------
// Scan pass 1: chunk end-states only (fp16 Bu, 16-deep load batches).
// grid = B*NCH = 512 blocks.
// ---------------------------------------------------------------------------
__global__ __launch_bounds__(PP)
void scan_ends_kernel() {
    int bc = blockIdx.x;
    int b = bc >> 6, c = bc & 63;
    int p = threadIdx.x;
    float ar = g_LbR[p], ai = g_LbI[p];
    float xr = 0.0f, xi = 0.0f;
    int m0 = b * LL + c * CHUNK;
#pragma unroll 1
    for (int l0 = 0; l0 < CHUNK; l0 += 16) {
        float br[16], bi16[16];
#pragma unroll
        for (int j = 0; j < 16; j++) {
            size_t idx = (size_t)(m0 + l0 + j) * N1 + p;
            br[j]   = __half2float(g_Buh[idx]);
            bi16[j] = __half2float(g_Buh[idx + PP]);
        }
#pragma unroll
        for (int j = 0; j < 16; j++) {
            float nr = fmaf(ar, xr, fmaf(-ai, xi, br[j]));
            float ni = fmaf(ar, xi, fmaf( ai, xr, bi16[j]));
            xr = nr; xi = ni;
        }
    }
    int base = (b * NCH + c) * PP + p;
    g_CEndR[base] = xr;
    g_CEndI[base] = xi;
}

// ---------------------------------------------------------------------------
// Scan pass 2: carry scan across chunks + state output.
// ---------------------------------------------------------------------------
__global__ __launch_bounds__(PP)
void scan_carry_kernel(float* __restrict__ out, int out_size) {
    int b = blockIdx.x;
    int p = threadIdx.x;
    float plr = g_PowR[CHUNK * PP + p];
    float pli = g_PowI[CHUNK * PP + p];
    float cr = 0.0f, ci = 0.0f;
#pragma unroll
    for (int c = 0; c < NCH; c++) {
        int base = (b * NCH + c) * PP + p;
        g_CInR[base] = cr;
        g_CInI[base] = ci;
        float er = g_CEndR[base], ei = g_CEndI[base];
        float nr = fmaf(plr, cr, fmaf(-pli, ci, er));
        float ni = fmaf(plr, ci, fmaf( pli, cr, ei));
        cr = nr; ci = ni;
    }
    if (out_size >= MH + 2 * BB * PP) {
        size_t tail = (size_t)MH + ((size_t)b * PP + p) * 2;
        out[tail]     = cr;
        out[tail + 1] = ci;
    } else {
        out[(size_t)MH + (size_t)b * PP + p] = cr;
    }
}

// ---------------------------------------------------------------------------
// Scan pass 3 (fused): re-scan chunk seeded with global carry-in, convert to
// single-plane fp16 fragments for GEMM2. grid = B*NCH = 512 blocks.
// ---------------------------------------------------------------------------
__global__ __launch_bounds__(256)
void scan_conv_kernel() {
    __shared__ float s[16][520];   // padded
    int bc = blockIdx.x;
    int b = bc >> 6, c = bc & 63;
    int p = threadIdx.x;
    int cb = (b * NCH + c) * PP + p;
    float xr = g_CInR[cb], xi = g_CInI[cb];
    float ar = g_LbR[p], ai = g_LbI[p];
    int m0 = b * LL + c * CHUNK;

#pragma unroll 1
    for (int g8 = 0; g8 < CHUNK / 16; g8++) {
        float br[16], bi16[16];
#pragma unroll
        for (int r = 0; r < 16; r++) {
            size_t idx = (size_t)(m0 + g8 * 16 + r) * N1 + p;
            br[r]   = __half2float(g_Buh[idx]);
            bi16[r] = __half2float(g_Buh[idx + PP]);
        }
#pragma unroll
        for (int r = 0; r < 16; r++) {
            float nr = fmaf(ar, xr, fmaf(-ai, xi, br[r]));
            float ni = fmaf(ar, xi, fmaf( ai, xr, bi16[r]));
            xr = nr; xi = ni;
            s[r][p]      = xr;
            s[r][p + PP] = xi;
        }
        __syncthreads();

        int mt = (m0 >> 4) + g8;
#pragma unroll
        for (int it = 0; it < 4; it++) {
            int task = threadIdx.x + it * 256;   // 0..1023
            int kst = task >> 5, lane = task & 31;
            int r0 = lane >> 2;
            int c0 = (kst << 4) + (lane & 3) * 2;
            float v[8] = { s[r0][c0],     s[r0][c0 + 1], s[r0 + 8][c0],     s[r0 + 8][c0 + 1],
                           s[r0][c0 + 8], s[r0][c0 + 9], s[r0 + 8][c0 + 8], s[r0 + 8][c0 + 9] };
            __half h[8];
#pragma unroll
            for (int e = 0; e < 8; e++) h[e] = __float2half(v[e]);
            uint4 hv = make_uint4(pk2h(h[0], h[1]), pk2h(h[2], h[3]),
                                  pk2h(h[4], h[5]), pk2h(h[6], h[7]));
            size_t i0 = ((size_t)mt * KTA + kst) * 32 + lane;
            g_XeF[i0] = hv;
        }
        __syncthreads();
    }
}

// ---------------------------------------------------------------------------
extern "C" void kernel_launch(void* const* d_in, const int* in_sizes, int n_in,
                              void* d_out, int out_size) {
    const float* u        = (const float*)d_in[0];  // (B,L,H)
    const float* Lre      = (const float*)d_in[1];  // (P,)
    const float* Lim      = (const float*)d_in[2];  // (P,)
    const float* Bmat     = (const float*)d_in[3];  // (P,H,2)
    const float* Cmat     = (const float*)d_in[4];  // (H,P,2)
    const float* Dv       = (const float*)d_in[5];  // (H,)
    const float* log_step = (const float*)d_in[6];  // (P,)
    float* out = (float*)d_out;

    void *pUeF, *pXeF, *pW1F, *pW2F, *pBuh, *pS1;
    cudaGetSymbolAddress(&pUeF, g_UeF);
    cudaGetSymbolAddress(&pXeF, g_XeF);
    cudaGetSymbolAddress(&pW1F, g_W1F);
    cudaGetSymbolAddress(&pW2F, g_W2F);
    cudaGetSymbolAddress(&pBuh, g_Buh);
    cudaGetSymbolAddress(&pS1,  g_invS1);

    // Fused prep: power table + Lambda_bar | W fragments | u fragments
    prep_kernel<<<PREP_BLOCKS, 256>>>(Lre, Lim, log_step, Bmat, Cmat, u);

    // GEMM1: Bu_h = fp16( (u @ W1') * invS1 )
    gemm1_kernel<<<dim3(4, 256), 256>>>(
        (const uint4*)pUeF, (const uint2*)pW1F, (__half*)pBuh, (const float*)pS1);

    scan_ends_kernel<<<BB * NCH, PP>>>();
    scan_carry_kernel<<<BB, PP>>>(out, out_size);
    scan_conv_kernel<<<BB * NCH, 256>>>();

    // GEMM2: out = X @ W2 + D*u  (u from fp16 fragments)
    gemm2_kernel<<<dim3(4, 256), 256>>>(
        (const uint4*)pXeF, (const uint2*)pW2F, out, (const uint4*)pUeF, Dv);
}